// round 1
// baseline (speedup 1.0000x reference)
#include <cuda_runtime.h>

#define NB 64
#define CIN 128
#define COUT 128
#define TT_DIM 128
#define JJ 25
#define JP 26
#define TTILE 4

// ---------------- scratch (no allocations allowed) ----------------
__device__ float g_xt_mean[NB * CIN * JJ];   // mean over T
__device__ float g_E[NB * JJ * JJ];          // adj + alpha * adj@dyn, per batch
__device__ float g_csf[NB * JJ];             // 1 + alpha * colsum(dyn)

typedef unsigned long long u64;

__device__ __forceinline__ u64 pack2(float lo, float hi) {
    u64 r; asm("mov.b64 %0, {%1,%2};" : "=l"(r) : "f"(lo), "f"(hi)); return r;
}
__device__ __forceinline__ void unpack2(u64 v, float& lo, float& hi) {
    asm("mov.b64 {%0,%1}, %2;" : "=f"(lo), "=f"(hi) : "l"(v));
}
__device__ __forceinline__ u64 ffma2(u64 a, u64 b, u64 c) {
    u64 d; asm("fma.rn.f32x2 %0, %1, %2, %3;" : "=l"(d) : "l"(a), "l"(b), "l"(c)); return d;
}

// ---------------- K1: temporal mean  x_t[b,c,j] = mean_t x[b,c,t,j] ----------------
__global__ void k1_mean(const float* __restrict__ x) {
    int c = blockIdx.x, b = blockIdx.y;
    __shared__ float s[TT_DIM * JJ];
    const float* p = x + ((size_t)(b * CIN + c) * TT_DIM + threadIdx.x) * JJ;
#pragma unroll
    for (int j = 0; j < JJ; j++) s[threadIdx.x * JJ + j] = p[j];
    __syncthreads();
    int j = threadIdx.x;
    if (j < JJ) {
        float acc = 0.f;
#pragma unroll 8
        for (int t = 0; t < TT_DIM; t++) acc += s[t * JJ + j];
        g_xt_mean[(b * CIN + c) * JJ + j] = acc * (1.0f / TT_DIM);
    }
}

// ---------------- K2: per-batch attention ->  E[b], csf[b] ----------------
__global__ void k2_attn(const float* __restrict__ adj,
                        const float* __restrict__ Wk, const float* __restrict__ bk,
                        const float* __restrict__ Wq, const float* __restrict__ bq,
                        const float* __restrict__ alphaPtr) {
    int b = blockIdx.x;
    int tid = threadIdx.x;  // 128 threads
    __shared__ float xt[CIN * JP];
    __shared__ float skk[COUT * JP];
    __shared__ float sqq[COUT * JP];
    __shared__ float sdyn[JJ * JP];

    for (int i = tid; i < CIN * JJ; i += 128) {
        int c = i / JJ, j = i - c * JJ;
        xt[c * JP + j] = g_xt_mean[b * CIN * JJ + i];
    }
    __syncthreads();

    {   // kk / qq : 1x1 convs on pooled features (thread = output channel)
        int o = tid;
        float ak[JJ], aq[JJ];
#pragma unroll
        for (int j = 0; j < JJ; j++) { ak[j] = 0.f; aq[j] = 0.f; }
        for (int c = 0; c < CIN; c++) {
            float wk = Wk[o * CIN + c], wq = Wq[o * CIN + c];
#pragma unroll
            for (int j = 0; j < JJ; j++) {
                float xv = xt[c * JP + j];
                ak[j] = fmaf(wk, xv, ak[j]);
                aq[j] = fmaf(wq, xv, aq[j]);
            }
        }
        float bko = bk[o], bqo = bq[o];
#pragma unroll
        for (int j = 0; j < JJ; j++) { skk[o * JP + j] = ak[j] + bko; sqq[o * JP + j] = aq[j] + bqo; }
    }
    __syncthreads();

    // scores[j,k] = sum_c qq[c,j]*kk[c,k] / sqrt(COUT)
    const float inv_scale = 0.08838834764831843f;  // 1/sqrt(128)
    for (int i = tid; i < JJ * JJ; i += 128) {
        int j = i / JJ, k = i - j * JJ;
        float acc = 0.f;
        for (int o = 0; o < COUT; o++) acc = fmaf(sqq[o * JP + j], skk[o * JP + k], acc);
        sdyn[j * JP + k] = acc * inv_scale;
    }
    __syncthreads();

    // row softmax over k
    if (tid < JJ) {
        int j = tid;
        float m = -1e30f;
#pragma unroll
        for (int k = 0; k < JJ; k++) m = fmaxf(m, sdyn[j * JP + k]);
        float e[JJ]; float s = 0.f;
#pragma unroll
        for (int k = 0; k < JJ; k++) { e[k] = expf(sdyn[j * JP + k] - m); s += e[k]; }
        float inv = 1.0f / s;
#pragma unroll
        for (int k = 0; k < JJ; k++) sdyn[j * JP + k] = e[k] * inv;
    }
    __syncthreads();

    float alpha = alphaPtr[0];
    // E = adj + alpha * adj @ dyn
    for (int i = tid; i < JJ * JJ; i += 128) {
        int j = i / JJ, k = i - j * JJ;
        float acc = 0.f;
#pragma unroll
        for (int m2 = 0; m2 < JJ; m2++) acc = fmaf(adj[j * JJ + m2], sdyn[m2 * JP + k], acc);
        g_E[b * JJ * JJ + i] = adj[j * JJ + k] + alpha * acc;
    }
    // csf[k] = 1 + alpha * sum_j dyn[j,k]
    if (tid < JJ) {
        int k = tid;
        float acc = 0.f;
#pragma unroll
        for (int j = 0; j < JJ; j++) acc += sdyn[j * JP + k];
        g_csf[b * JJ + k] = 1.0f + alpha * acc;
    }
}

// ---------------- K3: out = ReLU(BN( Ws @ x @ E + bias )) ----------------
// block = (b, 4 t's). 256 threads. Each thread: 2 adjacent output channels x (1 t x 26 cols).
#define K3_WS_STRIDE 130
#define K3_SMEM_FLOATS (CIN * K3_WS_STRIDE + CIN * TTILE * JP + JJ * JP + JP)

__global__ void __launch_bounds__(256, 1)
k3_main(const float* __restrict__ x, const float* __restrict__ Ws,
        const float* __restrict__ bs, const float* __restrict__ gamma,
        const float* __restrict__ beta, const float* __restrict__ rmean,
        const float* __restrict__ rvar, float* __restrict__ out) {
    extern __shared__ float sm[];
    float* wsT = sm;                            // [CIN][130] transposed weights
    float* xs  = wsT + CIN * K3_WS_STRIDE;      // [CIN][TTILE][JP]
    float* Es  = xs + CIN * TTILE * JP;         // [JJ][JP]
    float* csf = Es + JJ * JP;                  // [JP]

    int b = blockIdx.y;
    int t0 = blockIdx.x * TTILE;
    int tid = threadIdx.x;

    // stage Ws transposed (padded rows: conflict-light, 8B-aligned pairs)
    for (int i = tid; i < COUT * CIN; i += 256) {
        int o = i >> 7, c = i & 127;
        wsT[c * K3_WS_STRIDE + o] = Ws[i];
    }
    // stage x tile
    const float* xb = x + ((size_t)b * CIN * TT_DIM + t0) * JJ;
    for (int i = tid; i < CIN * TTILE * JJ; i += 256) {
        int c = i / (TTILE * JJ); int r = i - c * (TTILE * JJ);
        int t = r / JJ; int j = r - t * JJ;
        xs[c * (TTILE * JP) + t * JP + j] = xb[(size_t)c * TT_DIM * JJ + t * JJ + j];
    }
    for (int i = tid; i < CIN * TTILE; i += 256) xs[i * JP + JJ] = 0.f;  // pad col
    for (int i = tid; i < JJ * JJ; i += 256) {
        int j = i / JJ, k = i - j * JJ;
        Es[j * JP + k] = g_E[b * JJ * JJ + i];
    }
    if (tid < JJ) { Es[tid * JP + JJ] = 0.f; csf[tid] = g_csf[b * JJ + tid]; }
    if (tid == 255) csf[JJ] = 0.f;
    __syncthreads();

    int m = tid & 63;
    int t = tid >> 6;          // 0..3, one t per warp-pair
    int o0 = m * 2;            // two adjacent output channels
    const float* xrow = xs + t * JP;

    u64 acc0[13], acc1[13];
    u64 zero = pack2(0.f, 0.f);
#pragma unroll
    for (int q = 0; q < 13; q++) { acc0[q] = zero; acc1[q] = zero; }

    // GEMM over channels: y[o,t,j] = sum_c WsT[c][o] * x[c,t,j]   (FFMA2 over j-pairs)
#pragma unroll 2
    for (int c = 0; c < CIN; c++) {
        float2 wp = *(const float2*)&wsT[c * K3_WS_STRIDE + o0];
        u64 w0 = pack2(wp.x, wp.x);
        u64 w1 = pack2(wp.y, wp.y);
        const float* xr = xrow + c * (TTILE * JP);
#pragma unroll
        for (int q = 0; q < 13; q++) {
            u64 xv = *(const u64*)&xr[2 * q];
            acc0[q] = ffma2(w0, xv, acc0[q]);
            acc1[q] = ffma2(w1, xv, acc1[q]);
        }
    }

    // unpack y
    float y0[JP], y1[JP];
#pragma unroll
    for (int q = 0; q < 13; q++) {
        unpack2(acc0[q], y0[2 * q], y0[2 * q + 1]);
        unpack2(acc1[q], y1[2 * q], y1[2 * q + 1]);
    }

    // joint mixing: z[o,t,k] = sum_j y[o,t,j] * E[j,k]   (FFMA2 over k-pairs)
    u64 z0[13], z1[13];
#pragma unroll
    for (int q = 0; q < 13; q++) { z0[q] = zero; z1[q] = zero; }
#pragma unroll
    for (int j = 0; j < JJ; j++) {
        u64 a0 = pack2(y0[j], y0[j]);
        u64 a1 = pack2(y1[j], y1[j]);
        const float* er = Es + j * JP;
#pragma unroll
        for (int q = 0; q < 13; q++) {
            u64 ev = *(const u64*)&er[2 * q];
            z0[q] = ffma2(a0, ev, z0[q]);
            z1[q] = ffma2(a1, ev, z1[q]);
        }
    }

    float zz[2][JP];
#pragma unroll
    for (int q = 0; q < 13; q++) {
        unpack2(z0[q], zz[0][2 * q], zz[0][2 * q + 1]);
        unpack2(z1[q], zz[1][2 * q], zz[1][2 * q + 1]);
    }

    // epilogue: bias + BN(inference) + ReLU
    int tglob = t0 + t;
#pragma unroll
    for (int r = 0; r < 2; r++) {
        int o = o0 + r;
        float inv = gamma[o] * rsqrtf(rvar[o] + 1e-5f);
        float shift = beta[o] - rmean[o] * inv;
        float bso = bs[o];
        float* po = out + ((size_t)(b * COUT + o) * TT_DIM + tglob) * JJ;
#pragma unroll
        for (int k = 0; k < JJ; k++) {
            float pre = zz[r][k] + bso * csf[k];
            float v = fmaf(pre, inv, shift);
            po[k] = fmaxf(v, 0.f);
        }
    }
}

// ---------------- launch ----------------
extern "C" void kernel_launch(void* const* d_in, const int* in_sizes, int n_in,
                              void* d_out, int out_size) {
    const float* x     = (const float*)d_in[0];
    const float* adj   = (const float*)d_in[1];
    const float* Wk    = (const float*)d_in[2];
    const float* bk    = (const float*)d_in[3];
    const float* Wq    = (const float*)d_in[4];
    const float* bq    = (const float*)d_in[5];
    const float* Ws    = (const float*)d_in[6];
    const float* bs    = (const float*)d_in[7];
    const float* gamma = (const float*)d_in[8];
    const float* beta  = (const float*)d_in[9];
    const float* rmean = (const float*)d_in[10];
    const float* rvar  = (const float*)d_in[11];
    const float* alpha = (const float*)d_in[12];
    float* out = (float*)d_out;

    cudaFuncSetAttribute(k3_main, cudaFuncAttributeMaxDynamicSharedMemorySize,
                         K3_SMEM_FLOATS * (int)sizeof(float));

    k1_mean<<<dim3(CIN, NB), TT_DIM>>>(x);
    k2_attn<<<NB, 128>>>(adj, Wk, bk, Wq, bq, alpha);
    k3_main<<<dim3(TT_DIM / TTILE, NB), 256, K3_SMEM_FLOATS * (int)sizeof(float)>>>(
        x, Ws, bs, gamma, beta, rmean, rvar, out);
}

// round 3
// speedup vs baseline: 1.1885x; 1.1885x over previous
#include <cuda_runtime.h>
#include <cuda_bf16.h>

typedef unsigned int u32;
typedef unsigned long long u64;

#define NB 64
#define CIN 128
#define COUT 128
#define TT 128
#define JJ 25
#define JP 26

#define TSLAB 16            // t's per CTA
#define CHT 4               // t's per chunk
#define NCHUNK (TSLAB/CHT)  // 4
#define NN 104              // cols per chunk = 4 * 26 (j=25 is zero pad)
#define NTILES 13           // NN / 8
#define AP 136              // A smem pitch (elems) -> 272B rows, conflict-free ldmatrix
#define BP 104              // B smem pitch (elems) -> 208B rows, conflict-free trans ldmatrix
#define DP 103              // D staging pitch (fp32), odd -> conflict-free

// ---- smem byte offsets ----
#define SM_E      0
#define SM_CSF    (JJ*JP*4)                       // 2600
#define SM_A_HI   2816
#define SM_A_LO   (SM_A_HI + COUT*AP*2)           // +34816
#define SM_B_BASE (SM_A_LO + COUT*AP*2)           // 72448
#define B_SPLIT   (CIN*BP*2)                      // 26624
#define SM_B(buf, sp) (SM_B_BASE + (buf)*2*B_SPLIT + (sp)*B_SPLIT)
#define SMEM_TOTAL (SM_B_BASE + 4*B_SPLIT)        // 178944

// ---------------- scratch ----------------
__device__ float g_xt_mean[NB * CIN * JJ];
__device__ float g_E[NB * JJ * JJ];
__device__ float g_csf[NB * JJ];

// ---------------- helpers ----------------
__device__ __forceinline__ u64 pack2(float lo, float hi) {
    u64 r; asm("mov.b64 %0, {%1,%2};" : "=l"(r) : "f"(lo), "f"(hi)); return r;
}
__device__ __forceinline__ void unpack2(u64 v, float& lo, float& hi) {
    asm("mov.b64 {%0,%1}, %2;" : "=f"(lo), "=f"(hi) : "l"(v));
}
__device__ __forceinline__ u64 ffma2(u64 a, u64 b, u64 c) {
    u64 d; asm("fma.rn.f32x2 %0, %1, %2, %3;" : "=l"(d) : "l"(a), "l"(b), "l"(c)); return d;
}
__device__ __forceinline__ u32 smem_u32(const void* p) {
    u32 a; asm("{ .reg .u64 t; cvta.to.shared.u64 t, %1; cvt.u32.u64 %0, t; }" : "=r"(a) : "l"(p));
    return a;
}
__device__ __forceinline__ void ldsm_x4(u32* r, u32 addr) {
    asm volatile("ldmatrix.sync.aligned.m8n8.x4.shared.b16 {%0,%1,%2,%3}, [%4];"
        : "=r"(r[0]), "=r"(r[1]), "=r"(r[2]), "=r"(r[3]) : "r"(addr) : "memory");
}
__device__ __forceinline__ void ldsm_x4t(u32* r, u32 addr) {
    asm volatile("ldmatrix.sync.aligned.m8n8.x4.trans.shared.b16 {%0,%1,%2,%3}, [%4];"
        : "=r"(r[0]), "=r"(r[1]), "=r"(r[2]), "=r"(r[3]) : "r"(addr) : "memory");
}
__device__ __forceinline__ void ldsm_x2t(u32* r, u32 addr) {
    asm volatile("ldmatrix.sync.aligned.m8n8.x2.trans.shared.b16 {%0,%1}, [%2];"
        : "=r"(r[0]), "=r"(r[1]) : "r"(addr) : "memory");
}
__device__ __forceinline__ void mma_bf16(float* d, const u32* a, const u32* b) {
    asm volatile("mma.sync.aligned.m16n8k16.row.col.f32.bf16.bf16.f32 "
        "{%0,%1,%2,%3}, {%4,%5,%6,%7}, {%8,%9}, {%0,%1,%2,%3};"
        : "+f"(d[0]), "+f"(d[1]), "+f"(d[2]), "+f"(d[3])
        : "r"(a[0]), "r"(a[1]), "r"(a[2]), "r"(a[3]), "r"(b[0]), "r"(b[1]));
}
__device__ __forceinline__ u32 bf16pair(float v0, float v1) {
    __nv_bfloat16 h0 = __float2bfloat16(v0), h1 = __float2bfloat16(v1);
    return (u32)__bfloat16_as_ushort(h0) | ((u32)__bfloat16_as_ushort(h1) << 16);
}

// ---------------- K1: temporal mean (streaming) ----------------
__global__ void k1_mean(const float* __restrict__ x) {
    int b = blockIdx.y;
    int c = blockIdx.x * 8 + (threadIdx.x >> 5);
    int j = threadIdx.x & 31;
    if (j >= JJ) return;
    const float* p = x + ((size_t)(b * CIN + c) * TT) * JJ + j;
    float a0 = 0.f, a1 = 0.f, a2 = 0.f, a3 = 0.f;
#pragma unroll 8
    for (int t = 0; t < TT; t += 4) {
        a0 += p[t * JJ]; a1 += p[(t + 1) * JJ];
        a2 += p[(t + 2) * JJ]; a3 += p[(t + 3) * JJ];
    }
    g_xt_mean[(b * CIN + c) * JJ + j] = (a0 + a1 + a2 + a3) * (1.0f / TT);
}

// ---------------- K2: per-batch attention -> E[b], csf[b] ----------------
__global__ void k2_attn(const float* __restrict__ adj,
                        const float* __restrict__ Wk, const float* __restrict__ bk,
                        const float* __restrict__ Wq, const float* __restrict__ bq,
                        const float* __restrict__ alphaPtr) {
    int b = blockIdx.x;
    int tid = threadIdx.x;  // 128
    __shared__ float xt[CIN * JP];
    __shared__ float skk[COUT * JP];
    __shared__ float sqq[COUT * JP];
    __shared__ float sdyn[JJ * JP];

    for (int i = tid; i < CIN * JJ; i += 128) {
        int c = i / JJ, j = i - c * JJ;
        xt[c * JP + j] = g_xt_mean[b * CIN * JJ + i];
    }
    __syncthreads();
    {
        int o = tid;
        float ak[JJ], aq[JJ];
#pragma unroll
        for (int j = 0; j < JJ; j++) { ak[j] = 0.f; aq[j] = 0.f; }
        for (int c = 0; c < CIN; c++) {
            float wk = Wk[o * CIN + c], wq = Wq[o * CIN + c];
#pragma unroll
            for (int j = 0; j < JJ; j++) {
                float xv = xt[c * JP + j];
                ak[j] = fmaf(wk, xv, ak[j]);
                aq[j] = fmaf(wq, xv, aq[j]);
            }
        }
        float bko = bk[o], bqo = bq[o];
#pragma unroll
        for (int j = 0; j < JJ; j++) { skk[o * JP + j] = ak[j] + bko; sqq[o * JP + j] = aq[j] + bqo; }
    }
    __syncthreads();
    const float inv_scale = 0.08838834764831843f;  // 1/sqrt(128)
    for (int i = tid; i < JJ * JJ; i += 128) {
        int j = i / JJ, k = i - j * JJ;
        float acc = 0.f;
        for (int o = 0; o < COUT; o++) acc = fmaf(sqq[o * JP + j], skk[o * JP + k], acc);
        sdyn[j * JP + k] = acc * inv_scale;
    }
    __syncthreads();
    if (tid < JJ) {
        int j = tid;
        float m = -1e30f;
#pragma unroll
        for (int k = 0; k < JJ; k++) m = fmaxf(m, sdyn[j * JP + k]);
        float e[JJ]; float s = 0.f;
#pragma unroll
        for (int k = 0; k < JJ; k++) { e[k] = expf(sdyn[j * JP + k] - m); s += e[k]; }
        float inv = 1.0f / s;
#pragma unroll
        for (int k = 0; k < JJ; k++) sdyn[j * JP + k] = e[k] * inv;
    }
    __syncthreads();
    float alpha = alphaPtr[0];
    for (int i = tid; i < JJ * JJ; i += 128) {
        int j = i / JJ, k = i - j * JJ;
        float acc = 0.f;
#pragma unroll
        for (int m2 = 0; m2 < JJ; m2++) acc = fmaf(adj[j * JJ + m2], sdyn[m2 * JP + k], acc);
        g_E[b * JJ * JJ + i] = adj[j * JJ + k] + alpha * acc;
    }
    if (tid < JJ) {
        int k = tid;
        float acc = 0.f;
#pragma unroll
        for (int j = 0; j < JJ; j++) acc += sdyn[j * JP + k];
        g_csf[b * JJ + k] = 1.0f + alpha * acc;
    }
}

// ---------------- producer: x fp32 -> bf16 hi/lo into B[buf] ----------------
__device__ __forceinline__ void produce(char* sm, const float* __restrict__ x,
                                        int b, int slab, int ch, int tid) {
    int c = tid >> 1, h = tid & 1;
    int t0 = slab * TSLAB + ch * CHT;
    const float* px = x + ((size_t)(b * CIN + c) * TT + t0) * JJ + h * 50;
    int buf = ch & 1;
    char* bh = sm + SM_B(buf, 0) + c * (BP * 2);
    char* bl = sm + SM_B(buf, 1) + c * (BP * 2);
    float v[50];
#pragma unroll
    for (int i = 0; i < 25; ++i) {
        float2 t2 = *(const float2*)&px[2 * i];
        v[2 * i] = t2.x; v[2 * i + 1] = t2.y;
    }
#pragma unroll
    for (int tl = 0; tl < 2; ++tl) {
        int nb = h * 52 + tl * 26;
#pragma unroll
        for (int q = 0; q < 13; ++q) {
            float v0 = v[tl * 25 + 2 * q];
            float v1 = (q < 12) ? v[tl * 25 + 2 * q + 1] : 0.f;
            __nv_bfloat16 h0 = __float2bfloat16(v0), h1 = __float2bfloat16(v1);
            float l0 = v0 - __bfloat162float(h0), l1 = v1 - __bfloat162float(h1);
            *(u32*)(bh + (nb + 2 * q) * 2) =
                (u32)__bfloat16_as_ushort(h0) | ((u32)__bfloat16_as_ushort(h1) << 16);
            *(u32*)(bl + (nb + 2 * q) * 2) = bf16pair(l0, l1);
        }
    }
}

// ---------------- K3: mma.sync GEMM + mix + BN + ReLU ----------------
__global__ void __launch_bounds__(256, 1)
k3_main(const float* __restrict__ x, const float* __restrict__ Ws,
        const float* __restrict__ bs, const float* __restrict__ gamma,
        const float* __restrict__ beta, const float* __restrict__ rmean,
        const float* __restrict__ rvar, float* __restrict__ out) {
    extern __shared__ char sm[];
    u32 sbase = smem_u32(sm);
    int tid = threadIdx.x;
    int b = blockIdx.y, slab = blockIdx.x;
    float* Es  = (float*)(sm + SM_E);
    float* csf = (float*)(sm + SM_CSF);

    // stage E / csf
    for (int i = tid; i < JJ * JJ; i += 256) {
        int j = i / JJ, k = i - j * JJ;
        Es[j * JP + k] = g_E[b * JJ * JJ + i];
    }
    if (tid < JJ) { Es[tid * JP + JJ] = 0.f; csf[tid] = g_csf[b * JJ + tid]; }
    if (tid == 255) csf[JJ] = 0.f;

    // stage A = Ws as bf16 hi/lo, row-major [o][c], pitch AP
    {
        __nv_bfloat16* ah = (__nv_bfloat16*)(sm + SM_A_HI);
        __nv_bfloat16* al = (__nv_bfloat16*)(sm + SM_A_LO);
        for (int i = tid; i < COUT * CIN; i += 256) {
            int o = i >> 7, c = i & 127;
            float v = Ws[i];
            __nv_bfloat16 hb = __float2bfloat16(v);
            ah[o * AP + c] = hb;
            al[o * AP + c] = __float2bfloat16(v - __bfloat162float(hb));
        }
    }

    produce(sm, x, b, slab, 0, tid);
    __syncthreads();

    // per-thread constants
    int warp = tid >> 5, lane = tid & 31;
    int o0 = warp * 16;
    int gid = lane >> 2, tig = lane & 3;
    u32 arow  = (u32)(o0 + (lane & 15));
    u32 acsel = (u32)((lane >> 4) * 8);
    u32 brow  = (u32)((lane & 7) + ((lane >> 3) & 1) * 8);
    u32 bcsel = (u32)((lane >> 4) * 8);
    u32 brow2 = (u32)(lane & 15);

    int oo = tid & 127, th = tid >> 7;
    float inv   = gamma[oo] * rsqrtf(rvar[oo] + 1e-5f);
    float shift = beta[oo] - rmean[oo] * inv;
    float bso   = bs[oo];

    for (int ch = 0; ch < NCHUNK; ++ch) {
        int buf = ch & 1;
        float acc[NTILES][4];
#pragma unroll
        for (int nt = 0; nt < NTILES; ++nt)
#pragma unroll
            for (int r = 0; r < 4; ++r) acc[nt][r] = 0.f;

        // 3-term split GEMM: (Ahi,Bhi), (Ahi,Blo), (Alo,Bhi)
#pragma unroll
        for (int s = 0; s < 3; ++s) {
            u32 Ab = sbase + (u32)((s == 2) ? SM_A_LO : SM_A_HI);
            u32 Bb = sbase + (u32)SM_B(buf, (s == 1) ? 1 : 0);
#pragma unroll
            for (int kt = 0; kt < 8; ++kt) {
                u32 ar[4];
                ldsm_x4(ar, Ab + (arow * AP + (u32)(kt * 16) + acsel) * 2);
                u32 br[4];
#pragma unroll
                for (int ntp = 0; ntp < 6; ++ntp) {
                    ldsm_x4t(br, Bb + (((u32)(kt * 16) + brow) * BP + (u32)(ntp * 16) + bcsel) * 2);
                    mma_bf16(acc[2 * ntp], ar, br);
                    mma_bf16(acc[2 * ntp + 1], ar, br + 2);
                }
                u32 b2[2];
                ldsm_x2t(b2, Bb + (((u32)(kt * 16) + brow2) * BP + 96u) * 2);
                mma_bf16(acc[12], ar, b2);
            }
        }
        __syncthreads();  // everyone done reading B[buf]

        // stage D frags into (dead) B[buf] region as fp32 [o][n], pitch DP
        float* stg = (float*)(sm + SM_B(buf, 0));
#pragma unroll
        for (int nt = 0; nt < NTILES; ++nt) {
            int n0 = nt * 8 + tig * 2;
            int r0 = o0 + gid, r1 = r0 + 8;
            stg[r0 * DP + n0]     = acc[nt][0];
            stg[r0 * DP + n0 + 1] = acc[nt][1];
            stg[r1 * DP + n0]     = acc[nt][2];
            stg[r1 * DP + n0 + 1] = acc[nt][3];
        }
        if (ch + 1 < NCHUNK) produce(sm, x, b, slab, ch + 1, tid);  // fills B[1-buf]
        __syncthreads();

        // epilogue: joint mix + bias + BN + ReLU (thread = (o, 2 t's))
#pragma unroll
        for (int tt = 0; tt < 2; ++tt) {
            int tl = th * 2 + tt;
            const float* yrow = stg + oo * DP + tl * 26;
            u64 z[13]; u64 zero = pack2(0.f, 0.f);
#pragma unroll
            for (int q = 0; q < 13; q++) z[q] = zero;
#pragma unroll
            for (int j = 0; j < JJ; j++) {
                float yv = yrow[j];
                u64 a = pack2(yv, yv);
                const float* er = Es + j * JP;
#pragma unroll
                for (int q = 0; q < 13; q++) z[q] = ffma2(a, *(const u64*)&er[2 * q], z[q]);
            }
            float zk[26];
#pragma unroll
            for (int q = 0; q < 13; q++) unpack2(z[q], zk[2 * q], zk[2 * q + 1]);
            int tglob = slab * TSLAB + ch * CHT + tl;
            float* po = out + ((size_t)(b * COUT + oo) * TT + tglob) * JJ;
#pragma unroll
            for (int k = 0; k < JJ; k++) {
                float pre = zk[k] + bso * csf[k];
                po[k] = fmaxf(fmaf(pre, inv, shift), 0.f);
            }
        }
        // next iter's MMA reads B[1-buf] (written before 2nd sync); the sync
        // after that MMA orders it against overwriting B[1-buf]'s staging.
    }
}

// ---------------- launch ----------------
extern "C" void kernel_launch(void* const* d_in, const int* in_sizes, int n_in,
                              void* d_out, int out_size) {
    const float* x     = (const float*)d_in[0];
    const float* adj   = (const float*)d_in[1];
    const float* Wk    = (const float*)d_in[2];
    const float* bk    = (const float*)d_in[3];
    const float* Wq    = (const float*)d_in[4];
    const float* bq    = (const float*)d_in[5];
    const float* Ws    = (const float*)d_in[6];
    const float* bs    = (const float*)d_in[7];
    const float* gamma = (const float*)d_in[8];
    const float* beta  = (const float*)d_in[9];
    const float* rmean = (const float*)d_in[10];
    const float* rvar  = (const float*)d_in[11];
    const float* alpha = (const float*)d_in[12];
    float* out = (float*)d_out;

    cudaFuncSetAttribute(k3_main, cudaFuncAttributeMaxDynamicSharedMemorySize, SMEM_TOTAL);

    k1_mean<<<dim3(16, NB), 256>>>(x);
    k2_attn<<<NB, 128>>>(adj, Wk, bk, Wq, bq, alpha);
    k3_main<<<dim3(TT / TSLAB, NB), 256, SMEM_TOTAL>>>(x, Ws, bs, gamma, beta, rmean, rvar, out);
}

// round 4
// speedup vs baseline: 1.9246x; 1.6194x over previous
#include <cuda_runtime.h>
#include <cuda_fp16.h>

typedef unsigned int u32;
typedef unsigned long long u64;

#define NB 64
#define CIN 128
#define COUT 128
#define TT 128
#define JJ 25
#define JP 26

#define TSLAB 8             // t's per CTA
#define CHT 4               // t's per chunk
#define NCHUNK 2
#define NN 104              // n cols per chunk = 4 t * 26 (k=25 is zero pad)
#define NTILES 13
#define AP 136              // A smem pitch (halves)
#define BP 104              // B smem pitch (halves)
#define RAWP 101            // raw x pitch (floats), conflict-light

// ---- smem byte offsets ----
#define SM_E      0
#define SM_CSF    2600
#define SM_A_HI   2816
#define SM_A_LO   (SM_A_HI + COUT*AP*2)      // 37632
#define SM_BH     (SM_A_LO + COUT*AP*2)      // 72448
#define SM_BL     (SM_BH + CIN*BP*2)         // 99072
#define SM_RAW0   (SM_BL + CIN*BP*2)         // 125696
#define RAW_BYTES (CIN*RAWP*4)               // 51712
#define SM_RAW(b) (SM_RAW0 + (b)*RAW_BYTES)
#define SMEM_TOTAL (SM_RAW0 + 2*RAW_BYTES)   // 229120

// ---------------- scratch ----------------
__device__ float g_xt_mean[NB * CIN * JJ];
__device__ float g_E[NB * JJ * JJ];
__device__ float g_csf[NB * JJ];

// ---------------- helpers ----------------
__device__ __forceinline__ u64 pack2(float lo, float hi) {
    u64 r; asm("mov.b64 %0, {%1,%2};" : "=l"(r) : "f"(lo), "f"(hi)); return r;
}
__device__ __forceinline__ void unpack2(u64 v, float& lo, float& hi) {
    asm("mov.b64 {%0,%1}, %2;" : "=f"(lo), "=f"(hi) : "l"(v));
}
__device__ __forceinline__ u64 ffma2(u64 a, u64 b, u64 c) {
    u64 d; asm("fma.rn.f32x2 %0, %1, %2, %3;" : "=l"(d) : "l"(a), "l"(b), "l"(c)); return d;
}
__device__ __forceinline__ u32 smem_u32(const void* p) {
    u32 a; asm("{ .reg .u64 t; cvta.to.shared.u64 t, %1; cvt.u32.u64 %0, t; }" : "=r"(a) : "l"(p));
    return a;
}
__device__ __forceinline__ void ldsm_x4(u32* r, u32 addr) {
    asm volatile("ldmatrix.sync.aligned.m8n8.x4.shared.b16 {%0,%1,%2,%3}, [%4];"
        : "=r"(r[0]), "=r"(r[1]), "=r"(r[2]), "=r"(r[3]) : "r"(addr) : "memory");
}
__device__ __forceinline__ void ldsm_x4t(u32* r, u32 addr) {
    asm volatile("ldmatrix.sync.aligned.m8n8.x4.trans.shared.b16 {%0,%1,%2,%3}, [%4];"
        : "=r"(r[0]), "=r"(r[1]), "=r"(r[2]), "=r"(r[3]) : "r"(addr) : "memory");
}
__device__ __forceinline__ void ldsm_x2t(u32* r, u32 addr) {
    asm volatile("ldmatrix.sync.aligned.m8n8.x2.trans.shared.b16 {%0,%1}, [%2];"
        : "=r"(r[0]), "=r"(r[1]) : "r"(addr) : "memory");
}
__device__ __forceinline__ void mma_fp16(float* d, const u32* a, const u32* b) {
    asm volatile("mma.sync.aligned.m16n8k16.row.col.f32.f16.f16.f32 "
        "{%0,%1,%2,%3}, {%4,%5,%6,%7}, {%8,%9}, {%0,%1,%2,%3};"
        : "+f"(d[0]), "+f"(d[1]), "+f"(d[2]), "+f"(d[3])
        : "r"(a[0]), "r"(a[1]), "r"(a[2]), "r"(a[3]), "r"(b[0]), "r"(b[1]));
}
__device__ __forceinline__ void cp4(u32 dst, const void* src) {
    asm volatile("cp.async.ca.shared.global [%0], [%1], 4;" :: "r"(dst), "l"(src) : "memory");
}
#define CP_COMMIT() asm volatile("cp.async.commit_group;" ::: "memory")
#define CP_WAIT0()  asm volatile("cp.async.wait_group 0;" ::: "memory")

// ---------------- K1: temporal mean (streaming) ----------------
__global__ void k1_mean(const float* __restrict__ x) {
    int b = blockIdx.y;
    int c = blockIdx.x * 8 + (threadIdx.x >> 5);
    int j = threadIdx.x & 31;
    if (j >= JJ) return;
    const float* p = x + ((size_t)(b * CIN + c) * TT) * JJ + j;
    float a0 = 0.f, a1 = 0.f, a2 = 0.f, a3 = 0.f;
#pragma unroll 8
    for (int t = 0; t < TT; t += 4) {
        a0 += p[t * JJ]; a1 += p[(t + 1) * JJ];
        a2 += p[(t + 2) * JJ]; a3 += p[(t + 3) * JJ];
    }
    g_xt_mean[(b * CIN + c) * JJ + j] = (a0 + a1 + a2 + a3) * (1.0f / TT);
}

// ---------------- K2: per-batch attention -> E[b], csf[b] ----------------
__global__ void k2_attn(const float* __restrict__ adj,
                        const float* __restrict__ Wk, const float* __restrict__ bk,
                        const float* __restrict__ Wq, const float* __restrict__ bq,
                        const float* __restrict__ alphaPtr) {
    int b = blockIdx.x;
    int tid = threadIdx.x;  // 128
    __shared__ float xt[CIN * JP];
    __shared__ float skk[COUT * JP];
    __shared__ float sqq[COUT * JP];
    __shared__ float sdyn[JJ * JP];

    for (int i = tid; i < CIN * JJ; i += 128) {
        int c = i / JJ, j = i - c * JJ;
        xt[c * JP + j] = g_xt_mean[b * CIN * JJ + i];
    }
    __syncthreads();
    {
        int o = tid;
        float ak[JJ], aq[JJ];
#pragma unroll
        for (int j = 0; j < JJ; j++) { ak[j] = 0.f; aq[j] = 0.f; }
        for (int c = 0; c < CIN; c++) {
            float wk = Wk[o * CIN + c], wq = Wq[o * CIN + c];
#pragma unroll
            for (int j = 0; j < JJ; j++) {
                float xv = xt[c * JP + j];
                ak[j] = fmaf(wk, xv, ak[j]);
                aq[j] = fmaf(wq, xv, aq[j]);
            }
        }
        float bko = bk[o], bqo = bq[o];
#pragma unroll
        for (int j = 0; j < JJ; j++) { skk[o * JP + j] = ak[j] + bko; sqq[o * JP + j] = aq[j] + bqo; }
    }
    __syncthreads();
    const float inv_scale = 0.08838834764831843f;  // 1/sqrt(128)
    for (int i = tid; i < JJ * JJ; i += 128) {
        int j = i / JJ, k = i - j * JJ;
        float acc = 0.f;
        for (int o = 0; o < COUT; o++) acc = fmaf(sqq[o * JP + j], skk[o * JP + k], acc);
        sdyn[j * JP + k] = acc * inv_scale;
    }
    __syncthreads();
    if (tid < JJ) {
        int j = tid;
        float m = -1e30f;
#pragma unroll
        for (int k = 0; k < JJ; k++) m = fmaxf(m, sdyn[j * JP + k]);
        float e[JJ]; float s = 0.f;
#pragma unroll
        for (int k = 0; k < JJ; k++) { e[k] = expf(sdyn[j * JP + k] - m); s += e[k]; }
        float inv = 1.0f / s;
#pragma unroll
        for (int k = 0; k < JJ; k++) sdyn[j * JP + k] = e[k] * inv;
    }
    __syncthreads();
    float alpha = alphaPtr[0];
    for (int i = tid; i < JJ * JJ; i += 128) {
        int j = i / JJ, k = i - j * JJ;
        float acc = 0.f;
#pragma unroll
        for (int m2 = 0; m2 < JJ; m2++) acc = fmaf(adj[j * JJ + m2], sdyn[m2 * JP + k], acc);
        g_E[b * JJ * JJ + i] = adj[j * JJ + k] + alpha * acc;
    }
    if (tid < JJ) {
        int k = tid;
        float acc = 0.f;
#pragma unroll
        for (int j = 0; j < JJ; j++) acc += sdyn[j * JP + k];
        g_csf[b * JJ + k] = 1.0f + alpha * acc;
    }
}

// ---------------- K3 ----------------
__global__ void __launch_bounds__(256, 1)
k3_main(const float* __restrict__ x, const float* __restrict__ Ws,
        const float* __restrict__ bs, const float* __restrict__ gamma,
        const float* __restrict__ beta, const float* __restrict__ rmean,
        const float* __restrict__ rvar, float* __restrict__ out) {
    extern __shared__ char sm[];
    u32 sbase = smem_u32(sm);
    int tid = threadIdx.x;
    int b = blockIdx.y, slab = blockIdx.x;
    float* Es  = (float*)(sm + SM_E);
    float* csf = (float*)(sm + SM_CSF);

    // -------- prologue: cp.async raw chunk 0 (fully coalesced) --------
    {
        int t0 = slab * TSLAB;
        const float* xb = x + ((size_t)b * CIN * TT + t0) * JJ;
#pragma unroll
        for (int k = 0; k < 50; ++k) {
            int flat = tid + 256 * k;
            int c = flat / 100, col = flat - 100 * c;
            cp4(sbase + SM_RAW(0) + (u32)((c * RAWP + col) * 4),
                xb + (size_t)c * TT * JJ + col);
        }
        CP_COMMIT();
    }

    // -------- stage E / csf --------
    for (int i = tid; i < JJ * JJ; i += 256) {
        int j = i / JJ, k = i - j * JJ;
        Es[j * JP + k] = g_E[b * JJ * JJ + i];
    }
    if (tid < JJ) { Es[tid * JP + JJ] = 0.f; csf[tid] = g_csf[b * JJ + tid]; }
    if (tid == 255) csf[JJ] = 0.f;

    // -------- stage A = Ws as fp16 hi/lo, [o][c] pitch AP --------
    {
        __half* ah = (__half*)(sm + SM_A_HI);
        __half* al = (__half*)(sm + SM_A_LO);
        for (int i = tid; i < COUT * CIN; i += 256) {
            int o = i >> 7, c = i & 127;
            float v = Ws[i];
            __half hb = __float2half_rn(v);
            ah[o * AP + c] = hb;
            al[o * AP + c] = __float2half_rn(v - __half2float(hb));
        }
    }
    CP_WAIT0();
    __syncthreads();

    // -------- per-thread constants --------
    int warp = tid >> 5, lane = tid & 31;
    int o0 = warp * 16;
    int gid = lane >> 2, tig = lane & 3;
    u32 arow  = (u32)(o0 + (lane & 15));
    u32 acsel = (u32)((lane >> 4) * 8);
    u32 brow  = (u32)((lane & 7) + ((lane >> 3) & 1) * 8);
    u32 bcsel = (u32)((lane >> 4) * 8);
    u32 brow2 = (u32)(lane & 15);

    int o_a = o0 + gid, o_b = o_a + 8;
    float inv_a = gamma[o_a] * rsqrtf(rvar[o_a] + 1e-5f);
    float sh_a  = beta[o_a] - rmean[o_a] * inv_a;
    float bs_a  = bs[o_a];
    float inv_b = gamma[o_b] * rsqrtf(rvar[o_b] + 1e-5f);
    float sh_b  = beta[o_b] - rmean[o_b] * inv_b;
    float bs_b  = bs[o_b];

    int cmix = tid >> 1, hmix = tid & 1;

    for (int ch = 0; ch < NCHUNK; ++ch) {
        // prefetch next raw chunk
        if (ch + 1 < NCHUNK) {
            int t0n = slab * TSLAB + (ch + 1) * CHT;
            const float* xb = x + ((size_t)b * CIN * TT + t0n) * JJ;
#pragma unroll
            for (int k = 0; k < 50; ++k) {
                int flat = tid + 256 * k;
                int c = flat / 100, col = flat - 100 * c;
                cp4(sbase + SM_RAW(1) + (u32)((c * RAWP + col) * 4),
                    xb + (size_t)c * TT * JJ + col);
            }
            CP_COMMIT();
        }

        // -------- mix: X' = X * E  (fp32), split to fp16 hi/lo into B --------
        {
            const float* xr = (const float*)(sm + SM_RAW(ch & 1)) + cmix * RAWP + hmix * 50;
            u64 z[2][13];
            u64 zero = pack2(0.f, 0.f);
#pragma unroll
            for (int t2 = 0; t2 < 2; ++t2)
#pragma unroll
                for (int q = 0; q < 13; ++q) z[t2][q] = zero;
#pragma unroll
            for (int j = 0; j < JJ; ++j) {
                float x0 = xr[j], x1 = xr[25 + j];
                u64 xp0 = pack2(x0, x0), xp1 = pack2(x1, x1);
                const float* er = Es + j * JP;
                u64 e[13];
#pragma unroll
                for (int q = 0; q < 13; ++q) e[q] = *(const u64*)&er[2 * q];
#pragma unroll
                for (int q = 0; q < 13; ++q) {
                    z[0][q] = ffma2(xp0, e[q], z[0][q]);
                    z[1][q] = ffma2(xp1, e[q], z[1][q]);
                }
            }
            char* bh = sm + SM_BH + cmix * (BP * 2);
            char* bl = sm + SM_BL + cmix * (BP * 2);
#pragma unroll
            for (int t2 = 0; t2 < 2; ++t2) {
                int nb = (hmix * 2 + t2) * 26;
#pragma unroll
                for (int q = 0; q < 13; ++q) {
                    float f0, f1; unpack2(z[t2][q], f0, f1);
                    __half h0 = __float2half_rn(f0), h1 = __float2half_rn(f1);
                    __half l0 = __float2half_rn(f0 - __half2float(h0));
                    __half l1 = __float2half_rn(f1 - __half2float(h1));
                    *(u32*)(bh + (nb + 2 * q) * 2) =
                        (u32)__half_as_ushort(h0) | ((u32)__half_as_ushort(h1) << 16);
                    *(u32*)(bl + (nb + 2 * q) * 2) =
                        (u32)__half_as_ushort(l0) | ((u32)__half_as_ushort(l1) << 16);
                }
            }
        }
        __syncthreads();  // B ready

        // -------- MMA: 3-term fp16 split --------
        float acc[NTILES][4];
#pragma unroll
        for (int nt = 0; nt < NTILES; ++nt)
#pragma unroll
            for (int r = 0; r < 4; ++r) acc[nt][r] = 0.f;

#pragma unroll
        for (int s = 0; s < 3; ++s) {
            u32 Ab = sbase + (u32)((s == 2) ? SM_A_LO : SM_A_HI);
            u32 Bb = sbase + (u32)((s == 1) ? SM_BL : SM_BH);
#pragma unroll
            for (int kt = 0; kt < 8; ++kt) {
                u32 ar[4];
                ldsm_x4(ar, Ab + (arow * AP + (u32)(kt * 16) + acsel) * 2);
                u32 br[4];
#pragma unroll
                for (int ntp = 0; ntp < 6; ++ntp) {
                    ldsm_x4t(br, Bb + (((u32)(kt * 16) + brow) * BP + (u32)(ntp * 16) + bcsel) * 2);
                    mma_fp16(acc[2 * ntp], ar, br);
                    mma_fp16(acc[2 * ntp + 1], ar, br + 2);
                }
                u32 b2[2];
                ldsm_x2t(b2, Bb + (((u32)(kt * 16) + brow2) * BP + 96u) * 2);
                mma_fp16(acc[12], ar, b2);
            }
        }

        // -------- epilogue: bias + BN + ReLU, straight from regs --------
        {
            int tch = slab * TSLAB + ch * CHT;
            size_t rowa = ((size_t)(b * COUT + o_a) * TT + tch) * JJ;
            size_t rowb = ((size_t)(b * COUT + o_b) * TT + tch) * JJ;
#pragma unroll
            for (int nt = 0; nt < NTILES; ++nt) {
                int n0 = nt * 8 + tig * 2;
#pragma unroll
                for (int r = 0; r < 4; ++r) {
                    int n = n0 + (r & 1);
                    int t = n / 26, k = n - 26 * t;
                    if (k < JJ) {
                        float ck = csf[k];
                        float vinv = (r < 2) ? inv_a : inv_b;
                        float vsh  = (r < 2) ? sh_a  : sh_b;
                        float vbs  = (r < 2) ? bs_a  : bs_b;
                        size_t base = (r < 2) ? rowa : rowb;
                        float pre = acc[nt][r] + vbs * ck;
                        out[base + (size_t)t * JJ + k] = fmaxf(fmaf(pre, vinv, vsh), 0.f);
                    }
                }
            }
        }

        if (ch + 1 < NCHUNK) { CP_WAIT0(); }
        __syncthreads();  // B free for next mix; raw[next] visible
    }
}

// ---------------- launch ----------------
extern "C" void kernel_launch(void* const* d_in, const int* in_sizes, int n_in,
                              void* d_out, int out_size) {
    const float* x     = (const float*)d_in[0];
    const float* adj   = (const float*)d_in[1];
    const float* Wk    = (const float*)d_in[2];
    const float* bk    = (const float*)d_in[3];
    const float* Wq    = (const float*)d_in[4];
    const float* bq    = (const float*)d_in[5];
    const float* Ws    = (const float*)d_in[6];
    const float* bs    = (const float*)d_in[7];
    const float* gamma = (const float*)d_in[8];
    const float* beta  = (const float*)d_in[9];
    const float* rmean = (const float*)d_in[10];
    const float* rvar  = (const float*)d_in[11];
    const float* alpha = (const float*)d_in[12];
    float* out = (float*)d_out;

    cudaFuncSetAttribute(k3_main, cudaFuncAttributeMaxDynamicSharedMemorySize, SMEM_TOTAL);

    k1_mean<<<dim3(16, NB), 256>>>(x);
    k2_attn<<<NB, 128>>>(adj, Wk, bk, Wq, bq, alpha);
    k3_main<<<dim3(TT / TSLAB, NB), 256, SMEM_TOTAL>>>(x, Ws, bs, gamma, beta, rmean, rvar, out);
}

// round 6
// speedup vs baseline: 2.0290x; 1.0543x over previous
#include <cuda_runtime.h>
#include <cuda_fp16.h>

typedef unsigned int u32;
typedef unsigned long long u64;

#define NB 64
#define CIN 128
#define COUT 128
#define TT 128
#define JJ 25
#define JP 26

#define TSLAB 16            // t's per CTA
#define CHT 2               // t's per chunk
#define NCHUNK 8
#define NN 56               // padded cols per chunk (2*26 valid + 4 garbage)
#define NTILES 7
#define AP 136              // A smem pitch (halves) -> 272B rows (16B-aligned)
#define BP 56               // B smem pitch (halves) -> 112B rows (16B-aligned, conflict-free trans ldsm)
#define RAWP 53             // raw x pitch (floats)

// ---- smem byte offsets ----
#define SM_E      0
#define SM_CSF    2600
#define SM_A_HI   2816
#define SM_A_LO   37632
#define SM_B0     72448
#define B_HALF    14336                     // 128*56*2
#define B_BUF     28672                     // hi+lo
#define SM_BH(b)  (SM_B0 + (b)*B_BUF)
#define SM_BL(b)  (SM_BH(b) + B_HALF)
#define SM_RAW0   129792
#define RAW_BYTES 27136                     // 128*53*4
#define SM_RAW(b) (SM_RAW0 + (b)*RAW_BYTES)
#define SMEM_TOTAL 184064

// named barrier ids
#define BAR_FULL(b) (1 + (b))
#define BAR_FREE(b) (3 + (b))
#define BAR_PROD    5

// ---------------- scratch ----------------
__device__ float g_xt_mean[NB * CIN * JJ];
__device__ float g_E[NB * JJ * JJ];
__device__ float g_csf[NB * JJ];

// ---------------- helpers ----------------
__device__ __forceinline__ u64 pack2(float lo, float hi) {
    u64 r; asm("mov.b64 %0, {%1,%2};" : "=l"(r) : "f"(lo), "f"(hi)); return r;
}
__device__ __forceinline__ void unpack2(u64 v, float& lo, float& hi) {
    asm("mov.b64 {%0,%1}, %2;" : "=f"(lo), "=f"(hi) : "l"(v));
}
__device__ __forceinline__ u64 ffma2(u64 a, u64 b, u64 c) {
    u64 d; asm("fma.rn.f32x2 %0, %1, %2, %3;" : "=l"(d) : "l"(a), "l"(b), "l"(c)); return d;
}
__device__ __forceinline__ u32 smem_u32(const void* p) {
    u32 a; asm("{ .reg .u64 t; cvta.to.shared.u64 t, %1; cvt.u32.u64 %0, t; }" : "=r"(a) : "l"(p));
    return a;
}
__device__ __forceinline__ void ldsm_x4(u32* r, u32 addr) {
    asm volatile("ldmatrix.sync.aligned.m8n8.x4.shared.b16 {%0,%1,%2,%3}, [%4];"
        : "=r"(r[0]), "=r"(r[1]), "=r"(r[2]), "=r"(r[3]) : "r"(addr) : "memory");
}
__device__ __forceinline__ void ldsm_x4t(u32* r, u32 addr) {
    asm volatile("ldmatrix.sync.aligned.m8n8.x4.trans.shared.b16 {%0,%1,%2,%3}, [%4];"
        : "=r"(r[0]), "=r"(r[1]), "=r"(r[2]), "=r"(r[3]) : "r"(addr) : "memory");
}
__device__ __forceinline__ void ldsm_x2t(u32* r, u32 addr) {
    asm volatile("ldmatrix.sync.aligned.m8n8.x2.trans.shared.b16 {%0,%1}, [%2];"
        : "=r"(r[0]), "=r"(r[1]) : "r"(addr) : "memory");
}
__device__ __forceinline__ void mma_fp16(float* d, const u32* a, const u32* b) {
    asm volatile("mma.sync.aligned.m16n8k16.row.col.f32.f16.f16.f32 "
        "{%0,%1,%2,%3}, {%4,%5,%6,%7}, {%8,%9}, {%0,%1,%2,%3};"
        : "+f"(d[0]), "+f"(d[1]), "+f"(d[2]), "+f"(d[3])
        : "r"(a[0]), "r"(a[1]), "r"(a[2]), "r"(a[3]), "r"(b[0]), "r"(b[1]));
}
__device__ __forceinline__ void cp4(u32 dst, const void* src) {
    asm volatile("cp.async.ca.shared.global [%0], [%1], 4;" :: "r"(dst), "l"(src) : "memory");
}
#define CP_COMMIT() asm volatile("cp.async.commit_group;" ::: "memory")
#define CP_WAIT1()  asm volatile("cp.async.wait_group 1;" ::: "memory")
#define CP_WAITALL() asm volatile("cp.async.wait_group 0;" ::: "memory")
#define BAR_SYNC(id, cnt) asm volatile("bar.sync %0, %1;" :: "r"(id), "r"(cnt) : "memory")
#define BAR_ARRIVE(id, cnt) asm volatile("bar.arrive %0, %1;" :: "r"(id), "r"(cnt) : "memory")

// ---------------- K1: temporal mean (streaming) ----------------
__global__ void k1_mean(const float* __restrict__ x) {
    int b = blockIdx.y;
    int c = blockIdx.x * 8 + (threadIdx.x >> 5);
    int j = threadIdx.x & 31;
    if (j >= JJ) return;
    const float* p = x + ((size_t)(b * CIN + c) * TT) * JJ + j;
    float a0 = 0.f, a1 = 0.f, a2 = 0.f, a3 = 0.f;
    float a4 = 0.f, a5 = 0.f, a6 = 0.f, a7 = 0.f;
#pragma unroll 4
    for (int t = 0; t < TT; t += 8) {
        a0 += p[t * JJ];       a1 += p[(t + 1) * JJ];
        a2 += p[(t + 2) * JJ]; a3 += p[(t + 3) * JJ];
        a4 += p[(t + 4) * JJ]; a5 += p[(t + 5) * JJ];
        a6 += p[(t + 6) * JJ]; a7 += p[(t + 7) * JJ];
    }
    g_xt_mean[(b * CIN + c) * JJ + j] =
        ((a0 + a1) + (a2 + a3) + ((a4 + a5) + (a6 + a7))) * (1.0f / TT);
}

// ---------------- K2: per-batch attention -> E[b], csf[b] ----------------
__global__ void k2_attn(const float* __restrict__ adj,
                        const float* __restrict__ Wk, const float* __restrict__ bk,
                        const float* __restrict__ Wq, const float* __restrict__ bq,
                        const float* __restrict__ alphaPtr) {
    int b = blockIdx.x;
    int tid = threadIdx.x;  // 128
    __shared__ float xt[CIN * JP];
    __shared__ float skk[COUT * JP];
    __shared__ float sqq[COUT * JP];
    __shared__ float sdyn[JJ * JP];

    for (int i = tid; i < CIN * JJ; i += 128) {
        int c = i / JJ, j = i - c * JJ;
        xt[c * JP + j] = g_xt_mean[b * CIN * JJ + i];
    }
    __syncthreads();
    {
        int o = tid;
        float ak[JJ], aq[JJ];
#pragma unroll
        for (int j = 0; j < JJ; j++) { ak[j] = 0.f; aq[j] = 0.f; }
        for (int c = 0; c < CIN; c++) {
            float wk = Wk[o * CIN + c], wq = Wq[o * CIN + c];
#pragma unroll
            for (int j = 0; j < JJ; j++) {
                float xv = xt[c * JP + j];
                ak[j] = fmaf(wk, xv, ak[j]);
                aq[j] = fmaf(wq, xv, aq[j]);
            }
        }
        float bko = bk[o], bqo = bq[o];
#pragma unroll
        for (int j = 0; j < JJ; j++) { skk[o * JP + j] = ak[j] + bko; sqq[o * JP + j] = aq[j] + bqo; }
    }
    __syncthreads();
    const float inv_scale = 0.08838834764831843f;  // 1/sqrt(128)
    for (int i = tid; i < JJ * JJ; i += 128) {
        int j = i / JJ, k = i - j * JJ;
        float acc = 0.f;
        for (int o = 0; o < COUT; o++) acc = fmaf(sqq[o * JP + j], skk[o * JP + k], acc);
        sdyn[j * JP + k] = acc * inv_scale;
    }
    __syncthreads();
    if (tid < JJ) {
        int j = tid;
        float m = -1e30f;
#pragma unroll
        for (int k = 0; k < JJ; k++) m = fmaxf(m, sdyn[j * JP + k]);
        float e[JJ]; float s = 0.f;
#pragma unroll
        for (int k = 0; k < JJ; k++) { e[k] = expf(sdyn[j * JP + k] - m); s += e[k]; }
        float inv = 1.0f / s;
#pragma unroll
        for (int k = 0; k < JJ; k++) sdyn[j * JP + k] = e[k] * inv;
    }
    __syncthreads();
    float alpha = alphaPtr[0];
    for (int i = tid; i < JJ * JJ; i += 128) {
        int j = i / JJ, k = i - j * JJ;
        float acc = 0.f;
#pragma unroll
        for (int m2 = 0; m2 < JJ; m2++) acc = fmaf(adj[j * JJ + m2], sdyn[m2 * JP + k], acc);
        g_E[b * JJ * JJ + i] = adj[j * JJ + k] + alpha * acc;
    }
    if (tid < JJ) {
        int k = tid;
        float acc = 0.f;
#pragma unroll
        for (int j = 0; j < JJ; j++) acc += sdyn[j * JP + k];
        g_csf[b * JJ + k] = 1.0f + alpha * acc;
    }
}

// ---------------- K3: warp-specialized producer/consumer ----------------
__global__ void __launch_bounds__(512, 1)
k3_main(const float* __restrict__ x, const float* __restrict__ Ws,
        const float* __restrict__ bs, const float* __restrict__ gamma,
        const float* __restrict__ beta, const float* __restrict__ rmean,
        const float* __restrict__ rvar, float* __restrict__ out, int slab_off) {
    extern __shared__ char sm[];
    u32 sbase = smem_u32(sm);
    int tid = threadIdx.x;
    int b = blockIdx.y, slab = blockIdx.x + slab_off;
    float* Es  = (float*)(sm + SM_E);
    float* csf = (float*)(sm + SM_CSF);
    int t0slab = slab * TSLAB;

    bool is_prod = tid >= 256;
    int ptid = tid & 255;

    // ---- producers: kick off cp.async for chunks 0 and 1 ----
    if (is_prod) {
        const float* xb = x + ((size_t)b * CIN * TT + t0slab) * JJ;
#pragma unroll
        for (int cb = 0; cb < 2; ++cb) {
#pragma unroll
            for (int k = 0; k < 25; ++k) {
                int flat = ptid + 256 * k;
                int c = flat / 50, col = flat - 50 * c;
                cp4(sbase + SM_RAW(cb) + (u32)((c * RAWP + col) * 4),
                    xb + (size_t)c * TT * JJ + cb * (CHT * JJ) + col);
            }
            CP_COMMIT();
        }
    }

    // ---- all threads: stage E / csf / A ----
    for (int i = tid; i < JJ * JJ; i += 512) {
        int j = i / JJ, k = i - j * JJ;
        Es[j * JP + k] = g_E[b * JJ * JJ + i];
    }
    if (tid < JJ) { Es[tid * JP + JJ] = 0.f; csf[tid] = g_csf[b * JJ + tid]; }
    {
        __half* ah = (__half*)(sm + SM_A_HI);
        __half* al = (__half*)(sm + SM_A_LO);
        for (int i = tid; i < COUT * CIN; i += 512) {
            int o = i >> 7, c = i & 127;
            float v = Ws[i];
            __half hb = __float2half_rn(v);
            ah[o * AP + c] = hb;
            al[o * AP + c] = __float2half_rn(v - __half2float(hb));
        }
    }
    __syncthreads();

    if (!is_prod) {
        // ================= CONSUMERS (warps 0..7) =================
        int warp = tid >> 5, lane = tid & 31;
        int o0 = warp * 16;
        int gid = lane >> 2, tig = lane & 3;
        u32 arow  = (u32)(o0 + (lane & 15));
        u32 acsel = (u32)((lane >> 4) * 8);
        u32 brow  = (u32)((lane & 7) + ((lane >> 3) & 1) * 8);
        u32 bcsel = (u32)((lane >> 4) * 8);
        u32 brow2 = (u32)(lane & 15);

        int o_a = o0 + gid, o_b = o_a + 8;
        float inv_a = gamma[o_a] * rsqrtf(rvar[o_a] + 1e-5f);
        float sh_a  = beta[o_a] - rmean[o_a] * inv_a;
        float bs_a  = bs[o_a];
        float inv_b = gamma[o_b] * rsqrtf(rvar[o_b] + 1e-5f);
        float sh_b  = beta[o_b] - rmean[o_b] * inv_b;
        float bs_b  = bs[o_b];

        for (int ch = 0; ch < NCHUNK; ++ch) {
            int buf = ch & 1;
            BAR_SYNC(BAR_FULL(buf), 512);

            float acc[NTILES][4];
#pragma unroll
            for (int nt = 0; nt < NTILES; ++nt)
#pragma unroll
                for (int r = 0; r < 4; ++r) acc[nt][r] = 0.f;

#pragma unroll
            for (int s = 0; s < 3; ++s) {
                u32 Ab = sbase + (u32)((s == 2) ? SM_A_LO : SM_A_HI);
                u32 Bb = sbase + (u32)((s == 1) ? SM_BL(buf) : SM_BH(buf));
#pragma unroll
                for (int kt = 0; kt < 8; ++kt) {
                    u32 ar[4];
                    ldsm_x4(ar, Ab + (arow * AP + (u32)(kt * 16) + acsel) * 2);
                    u32 br[4];
#pragma unroll
                    for (int ntp = 0; ntp < 3; ++ntp) {
                        ldsm_x4t(br, Bb + (((u32)(kt * 16) + brow) * BP + (u32)(ntp * 16) + bcsel) * 2);
                        mma_fp16(acc[2 * ntp], ar, br);
                        mma_fp16(acc[2 * ntp + 1], ar, br + 2);
                    }
                    u32 b2[2];
                    ldsm_x2t(b2, Bb + (((u32)(kt * 16) + brow2) * BP + 48u) * 2);
                    mma_fp16(acc[6], ar, b2);
                }
            }
            BAR_ARRIVE(BAR_FREE(buf), 512);  // B[buf] free for producers

            // epilogue: bias + BN + ReLU
            int tch = t0slab + ch * CHT;
            size_t rowa = ((size_t)(b * COUT + o_a) * TT + tch) * JJ;
            size_t rowb = ((size_t)(b * COUT + o_b) * TT + tch) * JJ;
#pragma unroll
            for (int nt = 0; nt < NTILES; ++nt) {
                int n0 = nt * 8 + tig * 2;
#pragma unroll
                for (int r = 0; r < 4; ++r) {
                    int n = n0 + (r & 1);
                    int t = n / 26, k = n - 26 * t;
                    if (t < CHT && k < JJ) {
                        float ck = csf[k];
                        float vinv = (r < 2) ? inv_a : inv_b;
                        float vsh  = (r < 2) ? sh_a  : sh_b;
                        float vbs  = (r < 2) ? bs_a  : bs_b;
                        size_t base = (r < 2) ? rowa : rowb;
                        float pre = acc[nt][r] + vbs * ck;
                        out[base + (size_t)t * JJ + k] = fmaxf(fmaf(pre, vinv, vsh), 0.f);
                    }
                }
            }
        }
    } else {
        // ================= PRODUCERS (warps 8..15) =================
        int c = ptid >> 1, h = ptid & 1;
        const float* xb = x + ((size_t)b * CIN * TT + t0slab) * JJ;

        for (int ch = 0; ch < NCHUNK; ++ch) {
            int buf = ch & 1;
            if (ch < NCHUNK - 2) { CP_WAIT1(); } else { CP_WAITALL(); }
            if (ch >= 2) BAR_SYNC(BAR_FREE(buf), 512);
            BAR_SYNC(BAR_PROD, 256);  // raw[buf] fully landed (all producers' cps)

            // mix: z[t=h][k] = sum_j x[c][t][j] * E[j][k]
            const float* xr = (const float*)(sm + SM_RAW(buf)) + c * RAWP + h * JJ;
            float xv[JJ];
#pragma unroll
            for (int j = 0; j < JJ; ++j) xv[j] = xr[j];
            u64 z[13];
            u64 zero = pack2(0.f, 0.f);
#pragma unroll
            for (int q = 0; q < 13; ++q) z[q] = zero;
#pragma unroll
            for (int j = 0; j < JJ; ++j) {
                u64 xp = pack2(xv[j], xv[j]);
                const float* er = Es + j * JP;
#pragma unroll
                for (int q = 0; q < 13; ++q) z[q] = ffma2(xp, *(const u64*)&er[2 * q], z[q]);
            }
            // split to fp16 hi/lo and store B row c, cols h*26..h*26+25
            {
                char* bh = sm + SM_BH(buf) + (c * BP + h * 26) * 2;
                char* bl = sm + SM_BL(buf) + (c * BP + h * 26) * 2;
#pragma unroll
                for (int q = 0; q < 13; ++q) {
                    float f0, f1; unpack2(z[q], f0, f1);
                    __half h0 = __float2half_rn(f0), h1 = __float2half_rn(f1);
                    __half l0 = __float2half_rn(f0 - __half2float(h0));
                    __half l1 = __float2half_rn(f1 - __half2float(h1));
                    *(u32*)(bh + 4 * q) =
                        (u32)__half_as_ushort(h0) | ((u32)__half_as_ushort(h1) << 16);
                    *(u32*)(bl + 4 * q) =
                        (u32)__half_as_ushort(l0) | ((u32)__half_as_ushort(l1) << 16);
                }
            }
            BAR_ARRIVE(BAR_FULL(buf), 512);   // B[buf] ready for consumers
            BAR_SYNC(BAR_PROD, 256);          // all producers done reading raw[buf]

            if (ch + 2 < NCHUNK) {
#pragma unroll
                for (int k = 0; k < 25; ++k) {
                    int flat = ptid + 256 * k;
                    int cc = flat / 50, col = flat - 50 * cc;
                    cp4(sbase + SM_RAW(buf) + (u32)((cc * RAWP + col) * 4),
                        xb + (size_t)cc * TT * JJ + (ch + 2) * (CHT * JJ) + col);
                }
                CP_COMMIT();
            }
        }
    }
}

// ---------------- launch ----------------
extern "C" void kernel_launch(void* const* d_in, const int* in_sizes, int n_in,
                              void* d_out, int out_size) {
    const float* x     = (const float*)d_in[0];
    const float* adj   = (const float*)d_in[1];
    const float* Wk    = (const float*)d_in[2];
    const float* bk    = (const float*)d_in[3];
    const float* Wq    = (const float*)d_in[4];
    const float* bq    = (const float*)d_in[5];
    const float* Ws    = (const float*)d_in[6];
    const float* bs    = (const float*)d_in[7];
    const float* gamma = (const float*)d_in[8];
    const float* beta  = (const float*)d_in[9];
    const float* rmean = (const float*)d_in[10];
    const float* rvar  = (const float*)d_in[11];
    const float* alpha = (const float*)d_in[12];
    float* out = (float*)d_out;

    cudaFuncSetAttribute(k3_main, cudaFuncAttributeMaxDynamicSharedMemorySize, SMEM_TOTAL);

    k1_mean<<<dim3(16, NB), 256>>>(x);
    k2_attn<<<NB, 128>>>(adj, Wk, bk, Wq, bq, alpha);
    // k3 split in two half-grids (slabs 0..3 and 4..7)
    k3_main<<<dim3(4, NB), 512, SMEM_TOTAL>>>(x, Ws, bs, gamma, beta, rmean, rvar, out, 0);
    k3_main<<<dim3(4, NB), 512, SMEM_TOTAL>>>(x, Ws, bs, gamma, beta, rmean, rvar, out, 4);
}